// round 10
// baseline (speedup 1.0000x reference)
#include <cuda_runtime.h>
#include <cuda_bf16.h>
#include <cuda_fp16.h>
#include <mma.h>
#include <cstdint>

using namespace nvcuda;

#define Bd   2
#define Cc   128
#define Hd   64
#define Wd   512
#define HW   (Hd*Wd)          // 32768
#define NPIX (Bd*HW)          // 65536
#define EPS  1e-5f

#define LDW   136             // bf16 leading dim in smem (272B rows)
#define NPXT  64              // px tile per pass1 block
#define LDST  68              // f32 stage leading dim

// ---------------- device scratch (allocation-free) ----------------
__device__ __align__(16) __half        g_Yh[Cc * NPIX];  // [o][gp] Y in fp16
__device__ __align__(16) __nv_bfloat16 g_Whi[Cc * Cc];   // [o][c] fw*scale_f hi
__device__ __align__(16) __nv_bfloat16 g_Wlo[Cc * Cc];   // residual lo
__device__ float  g_hf[Cc];
__device__ float4 g_pw4[Cc];                             // {pw*sp (x3), hp}
__device__ float4 g_ew4[Cc];                             // {ew*se (x3), 0}
__device__ float  g_she[3];

// ---------------------------------------------------------------- prep
__global__ void prep_kernel(const float* __restrict__ fw,
                            const float* __restrict__ fg, const float* __restrict__ fb,
                            const float* __restrict__ fm, const float* __restrict__ fv,
                            const float* __restrict__ pw,
                            const float* __restrict__ pg, const float* __restrict__ pb,
                            const float* __restrict__ pm, const float* __restrict__ pv,
                            const float* __restrict__ ew,
                            const float* __restrict__ eg, const float* __restrict__ eb,
                            const float* __restrict__ em, const float* __restrict__ ev) {
    const int tid = threadIdx.x;
    if (blockIdx.x < 64) {
        int i = (blockIdx.x << 8) + tid;      // 0..16383
        int o = i >> 7;
        float sf = fg[o] * rsqrtf(fv[o] + EPS);
        float w = fw[i] * sf;
        __nv_bfloat16 hi = __float2bfloat16(w);
        __nv_bfloat16 lo = __float2bfloat16(w - __bfloat162float(hi));
        g_Whi[i] = hi;
        g_Wlo[i] = lo;
    } else if (tid < Cc) {
        int o = tid;
        float sf = fg[o] * rsqrtf(fv[o] + EPS);
        g_hf[o] = fb[o] - fm[o] * sf;
        float sp = pg[o] * rsqrtf(pv[o] + EPS);
        float hp = pb[o] - pm[o] * sp;
        g_pw4[o] = make_float4(pw[3*o]*sp, pw[3*o+1]*sp, pw[3*o+2]*sp, hp);
        float se0 = eg[0] * rsqrtf(ev[0] + EPS);
        float se1 = eg[1] * rsqrtf(ev[1] + EPS);
        float se2 = eg[2] * rsqrtf(ev[2] + EPS);
        g_ew4[o] = make_float4(ew[o]*se0, ew[Cc+o]*se1, ew[2*Cc+o]*se2, 0.f);
        if (o < 3) {
            float se = eg[o] * rsqrtf(ev[o] + EPS);
            g_she[o] = eb[o] - em[o] * se;
        }
    }
}

// ---------------------------------------------------------------- pass1 (wmma, 2 CTA/SM)
// Per block: D[128 out][64 px], 3-term bf16 split, f32 accum, fp16 Y store.
#define SEG_W 34816
#define SEG_F 17408
#define SM_TOT (2 * SEG_W + 2 * SEG_F)

__global__ void __launch_bounds__(256, 2)
pass1_wmma(const float* __restrict__ feat) {
    extern __shared__ __align__(16) char sm[];
    __nv_bfloat16* Whi = (__nv_bfloat16*)(sm);
    __nv_bfloat16* Wlo = (__nv_bfloat16*)(sm + SEG_W);
    __nv_bfloat16* Fhi = (__nv_bfloat16*)(sm + 2 * SEG_W);
    __nv_bfloat16* Flo = (__nv_bfloat16*)(sm + 2 * SEG_W + SEG_F);

    const int tid = threadIdx.x;
    const int gp0 = blockIdx.x * NPXT;
    const int b   = gp0 >> 15;
    const int p0  = gp0 & (HW - 1);

    // ---- W hi/lo into padded smem ----
    {
        const float4* shi = (const float4*)g_Whi;
        const float4* slo = (const float4*)g_Wlo;
        #pragma unroll
        for (int it = 0; it < 8; it++) {
            int idx = tid + (it << 8);           // 0..2047
            int r = idx >> 4, s = idx & 15;
            ((float4*)((char*)Whi + r * (LDW * 2)))[s] = shi[r * 16 + s];
            ((float4*)((char*)Wlo + r * (LDW * 2)))[s] = slo[r * 16 + s];
        }
    }

    // ---- F tile fp32 -> bf16 hi/lo, [px][k] padded smem ----
    {
        const float* fbase = feat + b * Cc * HW + p0;
        const int px = tid & 63;
        const int kg = tid >> 6;                 // 0..3 (32 k each)
        char* fhiRow = (char*)Fhi + px * (LDW * 2);
        char* floRow = (char*)Flo + px * (LDW * 2);
        #pragma unroll 8
        for (int j = 0; j < 16; j++) {
            int k = kg * 32 + 2 * j;
            float f0 = __ldg(fbase + k * HW + px);
            float f1 = __ldg(fbase + (k + 1) * HW + px);
            __nv_bfloat16 h0 = __float2bfloat16(f0);
            __nv_bfloat16 h1 = __float2bfloat16(f1);
            __nv_bfloat16 l0 = __float2bfloat16(f0 - __bfloat162float(h0));
            __nv_bfloat16 l1 = __float2bfloat16(f1 - __bfloat162float(h1));
            uint32_t vh = (uint32_t)__bfloat16_as_ushort(h0) | ((uint32_t)__bfloat16_as_ushort(h1) << 16);
            uint32_t vl = (uint32_t)__bfloat16_as_ushort(l0) | ((uint32_t)__bfloat16_as_ushort(l1) << 16);
            *(uint32_t*)(fhiRow + 2 * k) = vh;
            *(uint32_t*)(floRow + 2 * k) = vl;
        }
    }
    __syncthreads();

    // ---- wmma mainloop: 8 warps, each 32(out) x 32(px) ----
    const int wid = tid >> 5;
    const int wm  = wid & 3;
    const int wn  = wid >> 2;

    wmma::fragment<wmma::accumulator, 16, 16, 16, float> c[2][2];
    #pragma unroll
    for (int i = 0; i < 2; i++)
        #pragma unroll
        for (int j = 0; j < 2; j++) wmma::fill_fragment(c[i][j], 0.f);

    #pragma unroll
    for (int ks = 0; ks < 8; ks++) {
        const int k0 = ks * 16;
        wmma::fragment<wmma::matrix_a, 16, 16, 16, __nv_bfloat16, wmma::row_major> ah[2], al[2];
        wmma::fragment<wmma::matrix_b, 16, 16, 16, __nv_bfloat16, wmma::col_major> bh[2], bl[2];
        #pragma unroll
        for (int i = 0; i < 2; i++) {
            int m0 = wm * 32 + i * 16;
            wmma::load_matrix_sync(ah[i], Whi + m0 * LDW + k0, LDW);
            wmma::load_matrix_sync(al[i], Wlo + m0 * LDW + k0, LDW);
        }
        #pragma unroll
        for (int j = 0; j < 2; j++) {
            int n0 = wn * 32 + j * 16;
            wmma::load_matrix_sync(bh[j], Fhi + n0 * LDW + k0, LDW);
            wmma::load_matrix_sync(bl[j], Flo + n0 * LDW + k0, LDW);
        }
        #pragma unroll
        for (int i = 0; i < 2; i++)
            #pragma unroll
            for (int j = 0; j < 2; j++) {
                wmma::mma_sync(c[i][j], ah[i], bh[j], c[i][j]);
                wmma::mma_sync(c[i][j], ah[i], bl[j], c[i][j]);
                wmma::mma_sync(c[i][j], al[i], bh[j], c[i][j]);
            }
    }
    __syncthreads();

    // ---- stage accumulators (reuse F region), relu(+hf), fp16 STG ----
    float* stage = (float*)(sm + 2 * SEG_W);   // [128][LDST]
    #pragma unroll
    for (int i = 0; i < 2; i++)
        #pragma unroll
        for (int j = 0; j < 2; j++)
            wmma::store_matrix_sync(stage + (wm * 32 + i * 16) * LDST + wn * 32 + j * 16,
                                    c[i][j], LDST, wmma::mem_row_major);
    __syncthreads();

    const int lid = tid & 31;
    const int f4  = lid & 15;
    const int ro  = lid >> 4;
    #pragma unroll
    for (int j = 0; j < 8; j++) {
        int o = wid * 16 + 2 * j + ro;
        float hf = g_hf[o];
        float4 v = *(float4*)&stage[o * LDST + f4 * 4];
        __half2 h0 = __floats2half2_rn(fmaxf(v.x + hf, 0.f), fmaxf(v.y + hf, 0.f));
        __half2 h1 = __floats2half2_rn(fmaxf(v.z + hf, 0.f), fmaxf(v.w + hf, 0.f));
        uint2 pk;
        pk.x = *(uint32_t*)&h0;
        pk.y = *(uint32_t*)&h1;
        *(uint2*)(g_Yh + o * NPIX + gp0 + f4 * 4) = pk;
    }
}

// ---------------------------------------------------------------- pass2 (fused epilogue)
// 512 threads = 4 channel-groups x 128 px. In-block smem reduction of ew
// partials; writes geo AND cart_out (no fixup kernel, no g_E).
__global__ void __launch_bounds__(512)
pass2_kernel(const float* __restrict__ cart, const unsigned int* __restrict__ mk,
             float* __restrict__ out_geo, float* __restrict__ out_cart) {
    __shared__ float s_e[3][4][132];

    const int t   = threadIdx.x;
    const int px  = t & 127;
    const int grp = t >> 7;              // 0..3
    const int o0  = grp << 5;
    const int gp  = (blockIdx.x << 7) + px;
    const int b   = gp >> 15;
    const int p   = gp & (HW - 1);
    const int y   = p >> 9;
    const int x   = p & (Wd - 1);

    const float* cb = cart + b * 3 * HW;
    const float ccx = __ldg(cb + p);
    const float ccy = __ldg(cb + HW + p);
    const float ccz = __ldg(cb + 2 * HW + p);

    int   off[9];
    float am[9], rx[9], ry[9], rz[9];
#pragma unroll
    for (int kh = 0; kh < 3; kh++) {
#pragma unroll
        for (int kw = 0; kw < 3; kw++) {
            int n = kh * 3 + kw;
            int yy = y + kh - 1, xx = x + kw - 1;
            bool v = (yy >= 0) && (yy < Hd) && (xx >= 0) && (xx < Wd);
            int pn = yy * Wd + xx;
            int o  = v ? ((b << 15) + pn) : gp;
            off[n] = o;
            am[n]  = (v && (__ldg(mk + o) != 0u)) ? 1.f : 0.f;
            int pl = o & (HW - 1);
            rx[n] = __ldg(cb + pl) - ccx;
            ry[n] = __ldg(cb + HW + pl) - ccy;
            rz[n] = __ldg(cb + 2 * HW + pl) - ccz;
        }
    }

    float e0 = 0.f, e1 = 0.f, e2 = 0.f;
    float* og = out_geo + b * Cc * HW + p;

#pragma unroll 2
    for (int oc = 0; oc < 32; oc++) {
        const int o = o0 + oc;
        const float4 pwv = __ldg(&g_pw4[o]);
        const __half* Yo = g_Yh + o * NPIX;
        float gm = 0.f;
#pragma unroll
        for (int n = 0; n < 9; n++) {
            float pos = fmaxf(fmaf(pwv.x, rx[n], fmaf(pwv.y, ry[n], fmaf(pwv.z, rz[n], pwv.w))), 0.f);
            float fe  = __half2float(__ldg(Yo + off[n])) + pos;
            gm = fmaxf(gm, am[n] * fe);
        }
        og[o * HW] = gm;
        const float4 e = __ldg(&g_ew4[o]);
        e0 = fmaf(e.x, gm, e0);
        e1 = fmaf(e.y, gm, e1);
        e2 = fmaf(e.z, gm, e2);
    }

    s_e[0][grp][px] = e0;
    s_e[1][grp][px] = e1;
    s_e[2][grp][px] = e2;
    __syncthreads();

    if (grp == 0) {
        const float mc = (__ldg(mk + gp) != 0u) ? 1.f : 0.f;
#pragma unroll
        for (int k = 0; k < 3; k++) {
            float s = s_e[k][0][px] + s_e[k][1][px] + s_e[k][2][px] + s_e[k][3][px];
            int ci = (b * 3 + k) * HW + p;
            out_cart[ci] = __ldg(cart + ci) + (s + g_she[k]) * mc;
        }
    }
}

// ---------------------------------------------------------------- launch
extern "C" void kernel_launch(void* const* d_in, const int* in_sizes, int n_in,
                              void* d_out, int out_size) {
    const float* feat = (const float*)d_in[0];
    const float* cart = (const float*)d_in[1];
    const unsigned int* mask = (const unsigned int*)d_in[2];
    const float* pw = (const float*)d_in[3];
    const float* pg = (const float*)d_in[4];
    const float* pb = (const float*)d_in[5];
    const float* pm = (const float*)d_in[6];
    const float* pv = (const float*)d_in[7];
    const float* fw = (const float*)d_in[8];
    const float* fg = (const float*)d_in[9];
    const float* fb = (const float*)d_in[10];
    const float* fm = (const float*)d_in[11];
    const float* fv = (const float*)d_in[12];
    const float* ew = (const float*)d_in[13];
    const float* eg = (const float*)d_in[14];
    const float* eb = (const float*)d_in[15];
    const float* em = (const float*)d_in[16];
    const float* ev = (const float*)d_in[17];
    (void)in_sizes; (void)n_in; (void)out_size;

    float* out_geo  = (float*)d_out;                        // (B,128,H,W)
    float* out_cart = (float*)d_out + (size_t)Bd * Cc * HW; // (B,3,H,W)

    cudaFuncSetAttribute(pass1_wmma, cudaFuncAttributeMaxDynamicSharedMemorySize, SM_TOT);

    prep_kernel<<<65, 256>>>(fw, fg, fb, fm, fv, pw, pg, pb, pm, pv,
                             ew, eg, eb, em, ev);
    pass1_wmma<<<NPIX / NPXT, 256, SM_TOT>>>(feat);
    pass2_kernel<<<NPIX / 128, 512>>>(cart, mask, out_geo, out_cart);
}

// round 11
// speedup vs baseline: 1.4358x; 1.4358x over previous
#include <cuda_runtime.h>
#include <cuda_bf16.h>
#include <mma.h>
#include <cstdint>

using namespace nvcuda;

#define Bd   2
#define Cc   128
#define Hd   64
#define Wd   512
#define HW   (Hd*Wd)          // 32768
#define NPIX (Bd*HW)          // 65536
#define EPS  1e-5f

#define LDW   136             // bf16 leading dim in smem (272B rows)
#define NPXT  128             // px per pass1 block (2 sub-tiles of 64)
#define LDST  68              // f32 stage leading dim

// ---------------- device scratch (allocation-free) ----------------
__device__ __align__(16) float         g_Y[Cc * NPIX];   // [o][gp]
__device__ __align__(16) __nv_bfloat16 g_Whi[Cc * Cc];   // [o][c] fw*scale_f hi
__device__ __align__(16) __nv_bfloat16 g_Wlo[Cc * Cc];   // residual lo
__device__ __align__(16) float         g_E[12 * NPIX];   // [k*4+grp][gp] partial ew sums
__device__ float  g_hf[Cc];
__device__ float4 g_pw4[Cc];                             // {pw*sp (x3), hp}
__device__ float4 g_ew4[Cc];                             // {ew*se (x3), 0}
__device__ float  g_she[3];

__device__ __forceinline__ uint32_t smem_u32(const void* p) {
    uint32_t a;
    asm("{ .reg .u64 t; cvta.to.shared.u64 t, %1; cvt.u32.u64 %0, t; }" : "=r"(a) : "l"(p));
    return a;
}
__device__ __forceinline__ void cp_async16(uint32_t dst, const void* src) {
    asm volatile("cp.async.cg.shared.global [%0], [%1], 16;" :: "r"(dst), "l"(src) : "memory");
}

// ---------------------------------------------------------------- prep
__global__ void prep_kernel(const float* __restrict__ fw,
                            const float* __restrict__ fg, const float* __restrict__ fb,
                            const float* __restrict__ fm, const float* __restrict__ fv,
                            const float* __restrict__ pw,
                            const float* __restrict__ pg, const float* __restrict__ pb,
                            const float* __restrict__ pm, const float* __restrict__ pv,
                            const float* __restrict__ ew,
                            const float* __restrict__ eg, const float* __restrict__ eb,
                            const float* __restrict__ em, const float* __restrict__ ev) {
    const int tid = threadIdx.x;
    if (blockIdx.x < 64) {
        int i = (blockIdx.x << 8) + tid;      // 0..16383
        int o = i >> 7;
        float sf = fg[o] * rsqrtf(fv[o] + EPS);
        float w = fw[i] * sf;
        __nv_bfloat16 hi = __float2bfloat16(w);
        __nv_bfloat16 lo = __float2bfloat16(w - __bfloat162float(hi));
        g_Whi[i] = hi;
        g_Wlo[i] = lo;
    } else if (tid < Cc) {
        int o = tid;
        float sf = fg[o] * rsqrtf(fv[o] + EPS);
        g_hf[o] = fb[o] - fm[o] * sf;
        float sp = pg[o] * rsqrtf(pv[o] + EPS);
        float hp = pb[o] - pm[o] * sp;
        g_pw4[o] = make_float4(pw[3*o]*sp, pw[3*o+1]*sp, pw[3*o+2]*sp, hp);
        float se0 = eg[0] * rsqrtf(ev[0] + EPS);
        float se1 = eg[1] * rsqrtf(ev[1] + EPS);
        float se2 = eg[2] * rsqrtf(ev[2] + EPS);
        g_ew4[o] = make_float4(ew[o]*se0, ew[Cc+o]*se1, ew[2*Cc+o]*se2, 0.f);
        if (o < 3) {
            float se = eg[o] * rsqrtf(ev[o] + EPS);
            g_she[o] = eb[o] - em[o] * se;
        }
    }
}

// ---------------------------------------------------------------- pass1 (wmma, 2 CTA/SM)
// Per block: 2 sub-tiles of D[128 out][64 px]; W loaded ONCE via cp.async.
// smem: Whi(34816) | Wlo(34816) | Fhi(17408) | Flo(17408) = 104448 B.
#define SEG_W 34816
#define SEG_F 17408
#define SM_TOT (2 * SEG_W + 2 * SEG_F)

__global__ void __launch_bounds__(256, 2)
pass1_wmma(const float* __restrict__ feat) {
    extern __shared__ __align__(16) char sm[];
    __nv_bfloat16* Whi = (__nv_bfloat16*)(sm);
    __nv_bfloat16* Wlo = (__nv_bfloat16*)(sm + SEG_W);
    __nv_bfloat16* Fhi = (__nv_bfloat16*)(sm + 2 * SEG_W);
    __nv_bfloat16* Flo = (__nv_bfloat16*)(sm + 2 * SEG_W + SEG_F);

    const int tid = threadIdx.x;
    const int wid = tid >> 5;
    const int gpB = blockIdx.x * NPXT;
    const int b   = gpB >> 15;
    const int pB  = gpB & (HW - 1);

    // ---- W hi/lo into padded smem via cp.async (overlaps with F convert) ----
    {
        const uint32_t whiA = smem_u32(Whi);
        const uint32_t wloA = smem_u32(Wlo);
        #pragma unroll
        for (int it = 0; it < 8; it++) {
            int idx = tid + (it << 8);           // 0..2047
            int r = idx >> 4, s = idx & 15;
            uint32_t d = r * (LDW * 2) + s * 16;
            cp_async16(whiA + d, (const char*)g_Whi + (r * 128 + s * 8) * 2);
            cp_async16(wloA + d, (const char*)g_Wlo + (r * 128 + s * 8) * 2);
        }
        asm volatile("cp.async.commit_group;" ::: "memory");
    }

    const int px = tid & 63;
    const int kg = tid >> 6;                     // 0..3 (32 k each)
    const int wm = wid & 3;
    const int wn = wid >> 2;
    const int lid = tid & 31;
    const int f4  = lid & 15;
    const int ro  = lid >> 4;
    float* stage = (float*)(sm + 2 * SEG_W);     // [128][LDST] (reuses F region)

    #pragma unroll
    for (int sub = 0; sub < 2; sub++) {
        const int gp0 = gpB + sub * 64;
        const int p0  = pB + sub * 64;

        // ---- F tile fp32 -> bf16 hi/lo, [px][k] padded smem ----
        {
            const float* fbase = feat + b * Cc * HW + p0;
            char* fhiRow = (char*)Fhi + px * (LDW * 2);
            char* floRow = (char*)Flo + px * (LDW * 2);
            #pragma unroll 8
            for (int j = 0; j < 16; j++) {
                int k = kg * 32 + 2 * j;
                float f0 = __ldg(fbase + k * HW + px);
                float f1 = __ldg(fbase + (k + 1) * HW + px);
                __nv_bfloat16 h0 = __float2bfloat16(f0);
                __nv_bfloat16 h1 = __float2bfloat16(f1);
                __nv_bfloat16 l0 = __float2bfloat16(f0 - __bfloat162float(h0));
                __nv_bfloat16 l1 = __float2bfloat16(f1 - __bfloat162float(h1));
                uint32_t vh = (uint32_t)__bfloat16_as_ushort(h0) | ((uint32_t)__bfloat16_as_ushort(h1) << 16);
                uint32_t vl = (uint32_t)__bfloat16_as_ushort(l0) | ((uint32_t)__bfloat16_as_ushort(l1) << 16);
                *(uint32_t*)(fhiRow + 2 * k) = vh;
                *(uint32_t*)(floRow + 2 * k) = vl;
            }
        }
        if (sub == 0)
            asm volatile("cp.async.wait_group 0;" ::: "memory");
        __syncthreads();

        // ---- wmma mainloop: 8 warps, each 32(out) x 32(px) ----
        wmma::fragment<wmma::accumulator, 16, 16, 16, float> c[2][2];
        #pragma unroll
        for (int i = 0; i < 2; i++)
            #pragma unroll
            for (int j = 0; j < 2; j++) wmma::fill_fragment(c[i][j], 0.f);

        #pragma unroll
        for (int ks = 0; ks < 8; ks++) {
            const int k0 = ks * 16;
            wmma::fragment<wmma::matrix_a, 16, 16, 16, __nv_bfloat16, wmma::row_major> ah[2], al[2];
            wmma::fragment<wmma::matrix_b, 16, 16, 16, __nv_bfloat16, wmma::col_major> bh[2], bl[2];
            #pragma unroll
            for (int i = 0; i < 2; i++) {
                int m0 = wm * 32 + i * 16;
                wmma::load_matrix_sync(ah[i], Whi + m0 * LDW + k0, LDW);
                wmma::load_matrix_sync(al[i], Wlo + m0 * LDW + k0, LDW);
            }
            #pragma unroll
            for (int j = 0; j < 2; j++) {
                int n0 = wn * 32 + j * 16;
                wmma::load_matrix_sync(bh[j], Fhi + n0 * LDW + k0, LDW);
                wmma::load_matrix_sync(bl[j], Flo + n0 * LDW + k0, LDW);
            }
            #pragma unroll
            for (int i = 0; i < 2; i++)
                #pragma unroll
                for (int j = 0; j < 2; j++) {
                    wmma::mma_sync(c[i][j], ah[i], bh[j], c[i][j]);
                    wmma::mma_sync(c[i][j], ah[i], bl[j], c[i][j]);
                    wmma::mma_sync(c[i][j], al[i], bh[j], c[i][j]);
                }
        }
        __syncthreads();

        // ---- stage accumulators (reuse F region), relu(+hf), coalesced STG ----
        #pragma unroll
        for (int i = 0; i < 2; i++)
            #pragma unroll
            for (int j = 0; j < 2; j++)
                wmma::store_matrix_sync(stage + (wm * 32 + i * 16) * LDST + wn * 32 + j * 16,
                                        c[i][j], LDST, wmma::mem_row_major);
        __syncthreads();

        #pragma unroll
        for (int j = 0; j < 8; j++) {
            int o = wid * 16 + 2 * j + ro;
            float hf = g_hf[o];
            float4 v = *(float4*)&stage[o * LDST + f4 * 4];
            v.x = fmaxf(v.x + hf, 0.f);
            v.y = fmaxf(v.y + hf, 0.f);
            v.z = fmaxf(v.z + hf, 0.f);
            v.w = fmaxf(v.w + hf, 0.f);
            *(float4*)(g_Y + o * NPIX + gp0 + f4 * 4) = v;
        }
        if (sub == 0) __syncthreads();   // protect F region before next convert
    }
}

// ---------------------------------------------------------------- pass2 (R7-proven)
__global__ void __launch_bounds__(128)
pass2_kernel(const float* __restrict__ cart, const unsigned int* __restrict__ mk,
             float* __restrict__ out_geo) {
    const int gp = (blockIdx.x << 7) + threadIdx.x;
    const int grp = blockIdx.y;
    const int o0  = grp << 5;
    const int b  = gp >> 15;
    const int p  = gp & (HW - 1);
    const int y  = p >> 9;
    const int x  = p & (Wd - 1);

    const float* cb = cart + b * 3 * HW;
    const float ccx = __ldg(cb + p);
    const float ccy = __ldg(cb + HW + p);
    const float ccz = __ldg(cb + 2 * HW + p);

    int   off[9];
    float am[9], rx[9], ry[9], rz[9];
#pragma unroll
    for (int kh = 0; kh < 3; kh++) {
#pragma unroll
        for (int kw = 0; kw < 3; kw++) {
            int n = kh * 3 + kw;
            int yy = y + kh - 1, xx = x + kw - 1;
            bool v = (yy >= 0) && (yy < Hd) && (xx >= 0) && (xx < Wd);
            int pn = yy * Wd + xx;
            int o  = v ? ((b << 15) + pn) : gp;
            off[n] = o;
            am[n]  = (v && (__ldg(mk + o) != 0u)) ? 1.f : 0.f;
            int pl = o & (HW - 1);
            rx[n] = __ldg(cb + pl) - ccx;
            ry[n] = __ldg(cb + HW + pl) - ccy;
            rz[n] = __ldg(cb + 2 * HW + pl) - ccz;
        }
    }

    float e0 = 0.f, e1 = 0.f, e2 = 0.f;
    float* og = out_geo + b * Cc * HW + p;

#pragma unroll 2
    for (int oc = 0; oc < 32; oc++) {
        const int o = o0 + oc;
        const float4 pwv = __ldg(&g_pw4[o]);
        const float* Yo = g_Y + o * NPIX;
        float gm = 0.f;
#pragma unroll
        for (int n = 0; n < 9; n++) {
            float pos = fmaxf(fmaf(pwv.x, rx[n], fmaf(pwv.y, ry[n], fmaf(pwv.z, rz[n], pwv.w))), 0.f);
            float fe  = __ldg(Yo + off[n]) + pos;
            gm = fmaxf(gm, am[n] * fe);
        }
        og[o * HW] = gm;
        const float4 e = __ldg(&g_ew4[o]);
        e0 = fmaf(e.x, gm, e0);
        e1 = fmaf(e.y, gm, e1);
        e2 = fmaf(e.z, gm, e2);
    }

    g_E[(0 * 4 + grp) * NPIX + gp] = e0;
    g_E[(1 * 4 + grp) * NPIX + gp] = e1;
    g_E[(2 * 4 + grp) * NPIX + gp] = e2;
}

// ---------------------------------------------------------------- fixup (cart_out)
__global__ void __launch_bounds__(256)
fixup_kernel(const float* __restrict__ cart, const unsigned int* __restrict__ mk,
             float* __restrict__ out_cart) {
    const int gp = blockIdx.x * 256 + threadIdx.x;
    const int b  = gp >> 15;
    const int p  = gp & (HW - 1);
    const float mc = (__ldg(mk + gp) != 0u) ? 1.f : 0.f;
#pragma unroll
    for (int k = 0; k < 3; k++) {
        const float* Ek = g_E + k * 4 * NPIX;
        float s = Ek[gp] + Ek[NPIX + gp] + Ek[2 * NPIX + gp] + Ek[3 * NPIX + gp];
        int ci = (b * 3 + k) * HW + p;
        out_cart[ci] = __ldg(cart + ci) + (s + g_she[k]) * mc;
    }
}

// ---------------------------------------------------------------- launch
extern "C" void kernel_launch(void* const* d_in, const int* in_sizes, int n_in,
                              void* d_out, int out_size) {
    const float* feat = (const float*)d_in[0];
    const float* cart = (const float*)d_in[1];
    const unsigned int* mask = (const unsigned int*)d_in[2];
    const float* pw = (const float*)d_in[3];
    const float* pg = (const float*)d_in[4];
    const float* pb = (const float*)d_in[5];
    const float* pm = (const float*)d_in[6];
    const float* pv = (const float*)d_in[7];
    const float* fw = (const float*)d_in[8];
    const float* fg = (const float*)d_in[9];
    const float* fb = (const float*)d_in[10];
    const float* fm = (const float*)d_in[11];
    const float* fv = (const float*)d_in[12];
    const float* ew = (const float*)d_in[13];
    const float* eg = (const float*)d_in[14];
    const float* eb = (const float*)d_in[15];
    const float* em = (const float*)d_in[16];
    const float* ev = (const float*)d_in[17];
    (void)in_sizes; (void)n_in; (void)out_size;

    float* out_geo  = (float*)d_out;                        // (B,128,H,W)
    float* out_cart = (float*)d_out + (size_t)Bd * Cc * HW; // (B,3,H,W)

    cudaFuncSetAttribute(pass1_wmma, cudaFuncAttributeMaxDynamicSharedMemorySize, SM_TOT);

    prep_kernel<<<65, 256>>>(fw, fg, fb, fm, fv, pw, pg, pb, pm, pv,
                             ew, eg, eb, em, ev);
    pass1_wmma<<<NPIX / NPXT, 256, SM_TOT>>>(feat);
    dim3 g2(NPIX / 128, 4);
    pass2_kernel<<<g2, 128>>>(cart, mask, out_geo);
    fixup_kernel<<<NPIX / 256, 256>>>(cart, mask, out_cart);
}